// round 11
// baseline (speedup 1.0000x reference)
#include <cuda_runtime.h>
#include <cuda_fp16.h>
#include <math.h>
#include <stdint.h>

#define NN 4096
#define DD 256
#define BI 64      // passb: i-rows per CTA
#define BK 32      // passb: j per chunk
#define NCH (NN / BK)

// ---------------- scratch (device globals; no allocations allowed) ----------
__device__ float  g_Wh[3][NN * DD];      // fp32 Wh [i][d]
__device__ __half g_WhT[3][DD * NN];     // fp16 Wh transposed [d][j]
__device__ float4 g_ip[3][NN];           // {src, exp(src), exp(.2src), 0}
__device__ float4 g_jp[3][NN];           // {dst, exp(dst), exp(.2dst), 0}
__device__ float  g_out3[3][DD * NN];    // TRANSPOSED partials [d][i]

// ============================ helpers =======================================
__device__ __forceinline__ uint32_t smem_u32(const void* p) {
    uint32_t a;
    asm("{ .reg .u64 t; cvta.to.shared.u64 t, %1; cvt.u32.u64 %0, t; }"
        : "=r"(a) : "l"(p));
    return a;
}
__device__ __forceinline__ void cp16(uint32_t dst, const void* src) {
    asm volatile("cp.async.cg.shared.global [%0], [%1], 16;"
                 :: "r"(dst), "l"(src) : "memory");
}
#define CP_COMMIT() asm volatile("cp.async.commit_group;" ::: "memory")
#define CP_WAIT2()  asm volatile("cp.async.wait_group 2;" ::: "memory")
#define PROD_BAR()  asm volatile("bar.sync 1, 256;" ::: "memory")

#define LDM4(r0, r1, r2, r3, addr)                                             \
    asm volatile("ldmatrix.sync.aligned.m8n8.x4.shared.b16 {%0,%1,%2,%3}, [%4];" \
                 : "=r"(r0), "=r"(r1), "=r"(r2), "=r"(r3) : "r"(addr))

// ---------------------------------------------------------------------------
// Kernel 1: Wh_r = H @ W_r^T  (fp32 CUDA cores; ~0.8 G FMA)
// ---------------------------------------------------------------------------
__global__ void __launch_bounds__(256) wh_gemm_kernel(
    const float* __restrict__ H,
    const float* __restrict__ W1, const float* __restrict__ W2,
    const float* __restrict__ W3)
{
    const int r = blockIdx.y;
    const float* __restrict__ W = (r == 0) ? W1 : ((r == 1) ? W2 : W3);
    const int i0 = blockIdx.x * 32;

    __shared__ float Hs[32][32];
    __shared__ float Ws[32][256];

    const int tid = threadIdx.x;
    const int ty = tid >> 5;
    const int tx = tid & 31;

    float acc[4][8];
#pragma unroll
    for (int a = 0; a < 4; a++)
#pragma unroll
        for (int b = 0; b < 8; b++) acc[a][b] = 0.f;

    for (int k0 = 0; k0 < DD; k0 += 32) {
        {
            int row = tid >> 3, q = tid & 7;
            float4 v = *(const float4*)(H + (size_t)(i0 + row) * DD + k0 + q * 4);
            Hs[row][q * 4 + 0] = v.x; Hs[row][q * 4 + 1] = v.y;
            Hs[row][q * 4 + 2] = v.z; Hs[row][q * 4 + 3] = v.w;
        }
        {
            const float* wp = W + (size_t)tid * DD + k0;
#pragma unroll
            for (int q = 0; q < 8; q++) {
                float4 v = *(const float4*)(wp + q * 4);
                Ws[q * 4 + 0][tid] = v.x; Ws[q * 4 + 1][tid] = v.y;
                Ws[q * 4 + 2][tid] = v.z; Ws[q * 4 + 3][tid] = v.w;
            }
        }
        __syncthreads();
#pragma unroll
        for (int kk = 0; kk < 32; kk++) {
            float bv[8];
            *(float4*)&bv[0] = *(const float4*)&Ws[kk][tx * 4];
            *(float4*)&bv[4] = *(const float4*)&Ws[kk][128 + tx * 4];
#pragma unroll
            for (int a = 0; a < 4; a++) {
                float av = Hs[ty * 4 + a][kk];
#pragma unroll
                for (int b = 0; b < 8; b++) acc[a][b] += av * bv[b];
            }
        }
        __syncthreads();
    }

    float* out = g_Wh[r];
#pragma unroll
    for (int a = 0; a < 4; a++) {
        int i = i0 + ty * 4 + a;
        *(float4*)&out[(size_t)i * DD + tx * 4] =
            make_float4(acc[a][0], acc[a][1], acc[a][2], acc[a][3]);
        *(float4*)&out[(size_t)i * DD + 128 + tx * 4] =
            make_float4(acc[a][4], acc[a][5], acc[a][6], acc[a][7]);
    }
}

// ---------------------------------------------------------------------------
// Kernel 1b: transpose+convert  g_WhT[r][d][i] = (half)g_Wh[r][i][d]
// ---------------------------------------------------------------------------
__global__ void __launch_bounds__(256) transpose_kernel()
{
    const int r  = blockIdx.z;
    const int i0 = blockIdx.x * 32;
    const int d0 = blockIdx.y * 32;
    __shared__ float t[32][33];

    const int tid = threadIdx.x;
    const int row = tid >> 3;
    const int q   = tid & 7;

    float4 v = *(const float4*)(g_Wh[r] + (size_t)(i0 + row) * DD + d0 + q * 4);
    t[row][q * 4 + 0] = v.x; t[row][q * 4 + 1] = v.y;
    t[row][q * 4 + 2] = v.z; t[row][q * 4 + 3] = v.w;
    __syncthreads();

    uint32_t u0, u1;
    {
        __half h0 = __float2half_rn(t[q * 4 + 0][row]);
        __half h1 = __float2half_rn(t[q * 4 + 1][row]);
        __half h2 = __float2half_rn(t[q * 4 + 2][row]);
        __half h3 = __float2half_rn(t[q * 4 + 3][row]);
        u0 = (uint32_t)__half_as_ushort(h0) | ((uint32_t)__half_as_ushort(h1) << 16);
        u1 = (uint32_t)__half_as_ushort(h2) | ((uint32_t)__half_as_ushort(h3) << 16);
    }
    *(uint2*)&g_WhT[r][(size_t)(d0 + row) * NN + i0 + q * 4] = make_uint2(u0, u1);
}

// ---------------------------------------------------------------------------
// Kernel 2: src/dst projections + factorized-exp packs
// ---------------------------------------------------------------------------
__global__ void __launch_bounds__(256) srcdst_kernel(
    const float* __restrict__ a1, const float* __restrict__ a2,
    const float* __restrict__ a3)
{
    int gw = (blockIdx.x * 256 + threadIdx.x) >> 5;
    int lane = threadIdx.x & 31;
    int r = gw >> 12;
    int i = gw & (NN - 1);
    const float* __restrict__ av = (r == 0) ? a1 : ((r == 1) ? a2 : a3);
    const float* __restrict__ wh = g_Wh[r] + (size_t)i * DD;

    float s = 0.f, d = 0.f;
#pragma unroll
    for (int t = 0; t < 8; t++) {
        float w = wh[lane + 32 * t];
        s += w * av[lane + 32 * t];
        d += w * av[DD + lane + 32 * t];
    }
#pragma unroll
    for (int off = 16; off; off >>= 1) {
        s += __shfl_xor_sync(0xffffffffu, s, off);
        d += __shfl_xor_sync(0xffffffffu, d, off);
    }
    if (lane == 0) {
        g_ip[r][i] = make_float4(s, expf(s), expf(0.2f * s), 0.f);
        g_jp[r][i] = make_float4(d, expf(d), expf(0.2f * d), 0.f);
    }
}

// ---------------------------------------------------------------------------
// Kernel 3: pass-B on mma.sync, WARP-SPECIALIZED.
// 512 threads: warps 0-7 = consumers (mma, tile maps identical to R9),
//              warps 8-15 = producers (cp.async + A LDG + P build).
// CTA tile = 256 d x 64 i, grid 64x3 = 192 CTAs, 1 CTA/SM (regs-bound).
// Per chunk: one __syncthreads phase boundary; producers build P(c+1) while
// consumers mma(c) — genuine cross-warp overlap (no in-order-issue coupling).
//   C[d][i] = sum_j WhT[d][j] * P[i][j];  out3T[r][d][i] = C[d][i]/l_i
//   P[i][j] = A_ij * (s>0 ? E1_i*F1_j : E2_i*F2_j),  s = src_i + dst_j
// ---------------------------------------------------------------------------
#define SO_WH(s)  ((s) * 20480)            // 4 x (256 rows x 80B) = 81920
#define SO_JP(s)  (81920 + (s) * 512)      // 4 x 512 -> 83968
#define SO_P(b)   (83968 + (b) * 5120)     // 2 x (64 rows x 80B) -> 94208
#define SO_L      94208                    // float[64]
#define SMEM_PB   94464

__global__ void __launch_bounds__(512, 1) passb_mma_kernel(
    const int* __restrict__ A1, const int* __restrict__ A2,
    const int* __restrict__ A3)
{
    extern __shared__ char smem[];
    const uint32_t sb = smem_u32(smem);
    const int r = blockIdx.y;
    const int* __restrict__ A = (r == 0) ? A1 : ((r == 1) ? A2 : A3);
    const int i0 = blockIdx.x * BI;
    const __half*  __restrict__ WhT = g_WhT[r];
    const float4*  __restrict__ jp  = g_jp[r];

    const int tid  = threadIdx.x;
    const int w    = tid >> 5;
    const int lane = tid & 31;
    const bool is_prod = (tid >= 256);
    const int ptid = tid - 256;            // producer-local tid (0..255)

    float* s_l = (float*)(smem + SO_L);

    // ---- producer state ----
    const int pi  = ptid >> 2;             // 0..63
    const int pjq = ptid & 3;              // 0..3 -> j offset pjq*8
    const int whr = ptid >> 2, whp = ptid & 3;
    float src_i = 0.f, E1 = 0.f, E2 = 0.f;
    float l_acc = 0.f;
    const int* arow = 0;
    if (is_prod) {
        float4 ipv = g_ip[r][i0 + pi];
        src_i = ipv.x; E1 = ipv.y; E2 = ipv.z;
        arow = A + (size_t)(i0 + pi) * NN + pjq * 8;
    }

    // ---- consumer state: warp tile 64d x 32i (warps 0-7 = 4d x 2i) ----
    const int dwb = (w >> 1) * 64;
    const int nwb = (w & 1) * 32;
    const int ltile = lane >> 3, lwi = lane & 7;
    const uint32_t a_off =
        (uint32_t)(dwb + (ltile & 1) * 8 + lwi) * 80 + (ltile >> 1) * 16;
    const uint32_t b_off0 =
        (uint32_t)(nwb + ((ltile >> 1)) * 8 + lwi) * 80 + (ltile & 1) * 16;
    const uint32_t b_off1 =
        (uint32_t)(nwb + (2 + (ltile >> 1)) * 8 + lwi) * 80 + (ltile & 1) * 16;

    float c[4][4][4];
#pragma unroll
    for (int mi = 0; mi < 4; mi++)
#pragma unroll
        for (int ni = 0; ni < 4; ni++)
#pragma unroll
            for (int e = 0; e < 4; e++) c[mi][ni][e] = 0.f;

#define ISSUE_CHUNK(cc)                                                        \
    {                                                                          \
        const int j0_ = (cc) * BK;                                             \
        const int st_ = (cc) & 3;                                              \
        _Pragma("unroll")                                                      \
        for (int t = 0; t < 4; t++) {                                          \
            cp16(sb + SO_WH(st_) + (whr + t * 64) * 80 + whp * 16,             \
                 WhT + (size_t)(whr + t * 64) * NN + j0_ + whp * 8);           \
        }                                                                      \
        if (ptid < 32) cp16(sb + SO_JP(st_) + ptid * 16, jp + j0_ + ptid);     \
        CP_COMMIT();                                                           \
    }

#define BUILD_P(ST, PB)                                                        \
    {                                                                          \
        int aav[8] = {aa0.x, aa0.y, aa0.z, aa0.w, aa1.x, aa1.y, aa1.z, aa1.w}; \
        __half hh[8];                                                          \
        _Pragma("unroll")                                                      \
        for (int e = 0; e < 8; e++) {                                          \
            float4 jv = *(const float4*)(smem + SO_JP(ST) + pjq * 128 + e * 16); \
            float s = src_i + jv.x;                                            \
            float p = (s > 0.f) ? (E1 * jv.y) : (E2 * jv.z);                   \
            p = aav[e] ? p : 0.f;                                              \
            hh[e] = __float2half_rn(p);                                        \
            l_acc += __half2float(hh[e]);                                      \
        }                                                                      \
        uint4 pu;                                                              \
        pu.x = (uint32_t)__half_as_ushort(hh[0]) |                             \
               ((uint32_t)__half_as_ushort(hh[1]) << 16);                      \
        pu.y = (uint32_t)__half_as_ushort(hh[2]) |                             \
               ((uint32_t)__half_as_ushort(hh[3]) << 16);                      \
        pu.z = (uint32_t)__half_as_ushort(hh[4]) |                             \
               ((uint32_t)__half_as_ushort(hh[5]) << 16);                      \
        pu.w = (uint32_t)__half_as_ushort(hh[6]) |                             \
               ((uint32_t)__half_as_ushort(hh[7]) << 16);                      \
        *(uint4*)(smem + SO_P(PB) + pi * 80 + pjq * 16) = pu;                  \
    }

    int4 aa0 = make_int4(0, 0, 0, 0), aa1 = make_int4(0, 0, 0, 0);

    // ---- prologue ----
    if (is_prod) {
        ISSUE_CHUNK(0); ISSUE_CHUNK(1); ISSUE_CHUNK(2);
        aa0 = *(const int4*)arow;
        aa1 = *(const int4*)(arow + 4);
        CP_WAIT2();        // stage 0 arrived (producer threads)
    }
    __syncthreads();       // stage 0 visible to all producers
    if (is_prod) {
        BUILD_P(0, 0)
        aa0 = *(const int4*)(arow + BK);
        aa1 = *(const int4*)(arow + BK + 4);
    }

    for (int cch = 0; cch < NCH; cch++) {
        const int st = cch & 3;
        const int pb = cch & 1;
        __syncthreads();   // publishes P(cch); consumers done with stage st-1 & P(pb^1)

        if (is_prod) {
            // ---- producers: issue c+3, wait stage c+1, build P(c+1) ----
            if (cch + 3 < NCH) ISSUE_CHUNK(cch + 3) else CP_COMMIT();
            CP_WAIT2();    // stage cch+1 arrived (producer threads)
            PROD_BAR();    // make stage cch+1 visible across producer threads
            if (cch + 1 < NCH) {
                BUILD_P((cch + 1) & 3, pb ^ 1)
                if (cch + 2 < NCH) {
                    aa0 = *(const int4*)(arow + (cch + 2) * BK);
                    aa1 = *(const int4*)(arow + (cch + 2) * BK + 4);
                }
            }
        } else {
            // ---- consumers: mma(cch) from stage st and P buffer pb ----
            const uint32_t whs = sb + SO_WH(st);
            const uint32_t ps  = sb + SO_P(pb);
#pragma unroll
            for (int kt = 0; kt < 2; kt++) {
                uint32_t af[4][4], bf[4][2];
                LDM4(bf[0][0], bf[0][1], bf[1][0], bf[1][1],
                     ps + b_off0 + kt * 32);
                LDM4(bf[2][0], bf[2][1], bf[3][0], bf[3][1],
                     ps + b_off1 + kt * 32);
#pragma unroll
                for (int mi = 0; mi < 4; mi++)
                    LDM4(af[mi][0], af[mi][1], af[mi][2], af[mi][3],
                         whs + a_off + mi * 1280 + kt * 32);
#pragma unroll
                for (int ni = 0; ni < 4; ni++)
#pragma unroll
                    for (int mi = 0; mi < 4; mi++) {
                        asm volatile(
                            "mma.sync.aligned.m16n8k16.row.col.f32.f16.f16.f32 "
                            "{%0,%1,%2,%3}, {%4,%5,%6,%7}, {%8,%9}, {%0,%1,%2,%3};"
                            : "+f"(c[mi][ni][0]), "+f"(c[mi][ni][1]),
                              "+f"(c[mi][ni][2]), "+f"(c[mi][ni][3])
                            : "r"(af[mi][0]), "r"(af[mi][1]),
                              "r"(af[mi][2]), "r"(af[mi][3]),
                              "r"(bf[ni][0]), "r"(bf[ni][1]));
                    }
            }
        }
    }

    // ---- row sums -> 1/l (producers hold l_acc; 4 threads per i-row) ----
    __syncthreads();
    if (is_prod) {
        l_acc += __shfl_xor_sync(0xffffffffu, l_acc, 1);
        l_acc += __shfl_xor_sync(0xffffffffu, l_acc, 2);
        if ((ptid & 3) == 0) s_l[pi] = l_acc;
    }
    __syncthreads();
    if (tid < BI) {
        float l = s_l[tid];
        s_l[tid] = (l > 0.f) ? (1.f / l) : 0.f;
    }
    __syncthreads();

    // ---- epilogue: consumers store scaled transposed partials ----
    if (!is_prod) {
        float* T = g_out3[r];
#pragma unroll
        for (int ni = 0; ni < 4; ni++) {
            int icol = nwb + ni * 8 + (lane & 3) * 2;
            float iv0 = s_l[icol];
            float iv1 = s_l[icol + 1];
#pragma unroll
            for (int mi = 0; mi < 4; mi++) {
                int d = dwb + mi * 16 + (lane >> 2);
                *(float2*)&T[(size_t)d * NN + i0 + icol] =
                    make_float2(c[mi][ni][0] * iv0, c[mi][ni][1] * iv1);
                *(float2*)&T[(size_t)(d + 8) * NN + i0 + icol] =
                    make_float2(c[mi][ni][2] * iv0, c[mi][ni][3] * iv1);
            }
        }
    }
}

// ---------------------------------------------------------------------------
// Kernel 4: out[i][d] = sum_r out3T[r][d][i] + bias[d]
// ---------------------------------------------------------------------------
__global__ void __launch_bounds__(256) combine_t_kernel(
    const float* __restrict__ bias, float* __restrict__ out)
{
    const int i0 = blockIdx.x * 32;
    const int d0 = blockIdx.y * 32;
    __shared__ float t[32][33];

    const int tid = threadIdx.x;
    const int ty = tid >> 5;
    const int tx = tid & 31;

#pragma unroll
    for (int s = 0; s < 4; s++) {
        int dl = ty + s * 8;
        size_t off = (size_t)(d0 + dl) * NN + i0 + tx;
        t[dl][tx] = g_out3[0][off] + g_out3[1][off] + g_out3[2][off];
    }
    __syncthreads();

    const int il = tid >> 3;
    const int dq = (tid & 7) * 4;
    float4 b = *(const float4*)&bias[d0 + dq];
    float4 v;
    v.x = t[dq + 0][il] + b.x;
    v.y = t[dq + 1][il] + b.y;
    v.z = t[dq + 2][il] + b.z;
    v.w = t[dq + 3][il] + b.w;
    *(float4*)&out[(size_t)(i0 + il) * DD + d0 + dq] = v;
}

// ---------------------------------------------------------------------------
extern "C" void kernel_launch(void* const* d_in, const int* in_sizes, int n_in,
                              void* d_out, int out_size)
{
    const float* H    = (const float*)d_in[0];
    const float* W1   = (const float*)d_in[1];
    const float* W2   = (const float*)d_in[2];
    const float* W3   = (const float*)d_in[3];
    const float* a1   = (const float*)d_in[4];
    const float* a2   = (const float*)d_in[5];
    const float* a3   = (const float*)d_in[6];
    const float* bias = (const float*)d_in[7];
    const int*   A1   = (const int*)d_in[8];
    const int*   A2   = (const int*)d_in[9];
    const int*   A3   = (const int*)d_in[10];
    float* out = (float*)d_out;

    dim3 wh_grid(NN / 32, 3);
    wh_gemm_kernel<<<wh_grid, 256>>>(H, W1, W2, W3);

    dim3 tr_grid(NN / 32, DD / 32, 3);
    transpose_kernel<<<tr_grid, 256>>>();

    srcdst_kernel<<<3 * NN / 8, 256>>>(a1, a2, a3);

    cudaFuncSetAttribute(passb_mma_kernel,
                         cudaFuncAttributeMaxDynamicSharedMemorySize, SMEM_PB);
    dim3 pb_grid(NN / BI, 3);
    passb_mma_kernel<<<pb_grid, 512, SMEM_PB>>>(A1, A2, A3);

    dim3 cb_grid(NN / 32, DD / 32);
    combine_t_kernel<<<cb_grid, 256>>>(bias, out);
}

// round 12
// speedup vs baseline: 1.1935x; 1.1935x over previous
#include <cuda_runtime.h>
#include <cuda_fp16.h>
#include <math.h>
#include <stdint.h>

#define NN 4096
#define DD 256
#define BI 64      // passb: i-rows per CTA
#define BK 64      // passb: j per chunk
#define NCH (NN / BK)
#define WROW 144   // smem row stride bytes (64 halves = 128B + 16B pad)

// ---------------- scratch (device globals; no allocations allowed) ----------
__device__ float  g_Wh[3][NN * DD];      // fp32 Wh [i][d]
__device__ __half g_WhT[3][DD * NN];     // fp16 Wh transposed [d][j]
__device__ float4 g_ip[3][NN];           // {src, exp(src), exp(.2src), 0}
__device__ float4 g_jp[3][NN];           // {dst, exp(dst), exp(.2dst), 0}
__device__ float  g_out3[3][DD * NN];    // TRANSPOSED partials [d][i]

// ============================ helpers =======================================
__device__ __forceinline__ uint32_t smem_u32(const void* p) {
    uint32_t a;
    asm("{ .reg .u64 t; cvta.to.shared.u64 t, %1; cvt.u32.u64 %0, t; }"
        : "=r"(a) : "l"(p));
    return a;
}
__device__ __forceinline__ void cp16(uint32_t dst, const void* src) {
    asm volatile("cp.async.cg.shared.global [%0], [%1], 16;"
                 :: "r"(dst), "l"(src) : "memory");
}
#define CP_COMMIT() asm volatile("cp.async.commit_group;" ::: "memory")
#define CP_WAIT1()  asm volatile("cp.async.wait_group 1;" ::: "memory")

#define LDM4(r0, r1, r2, r3, addr)                                             \
    asm volatile("ldmatrix.sync.aligned.m8n8.x4.shared.b16 {%0,%1,%2,%3}, [%4];" \
                 : "=r"(r0), "=r"(r1), "=r"(r2), "=r"(r3) : "r"(addr))

// ---------------------------------------------------------------------------
// Kernel 1: Wh_r = H @ W_r^T  (fp32 CUDA cores; ~0.8 G FMA)
// ---------------------------------------------------------------------------
__global__ void __launch_bounds__(256) wh_gemm_kernel(
    const float* __restrict__ H,
    const float* __restrict__ W1, const float* __restrict__ W2,
    const float* __restrict__ W3)
{
    const int r = blockIdx.y;
    const float* __restrict__ W = (r == 0) ? W1 : ((r == 1) ? W2 : W3);
    const int i0 = blockIdx.x * 32;

    __shared__ float Hs[32][32];
    __shared__ float Ws[32][256];

    const int tid = threadIdx.x;
    const int ty = tid >> 5;
    const int tx = tid & 31;

    float acc[4][8];
#pragma unroll
    for (int a = 0; a < 4; a++)
#pragma unroll
        for (int b = 0; b < 8; b++) acc[a][b] = 0.f;

    for (int k0 = 0; k0 < DD; k0 += 32) {
        {
            int row = tid >> 3, q = tid & 7;
            float4 v = *(const float4*)(H + (size_t)(i0 + row) * DD + k0 + q * 4);
            Hs[row][q * 4 + 0] = v.x; Hs[row][q * 4 + 1] = v.y;
            Hs[row][q * 4 + 2] = v.z; Hs[row][q * 4 + 3] = v.w;
        }
        {
            const float* wp = W + (size_t)tid * DD + k0;
#pragma unroll
            for (int q = 0; q < 8; q++) {
                float4 v = *(const float4*)(wp + q * 4);
                Ws[q * 4 + 0][tid] = v.x; Ws[q * 4 + 1][tid] = v.y;
                Ws[q * 4 + 2][tid] = v.z; Ws[q * 4 + 3][tid] = v.w;
            }
        }
        __syncthreads();
#pragma unroll
        for (int kk = 0; kk < 32; kk++) {
            float bv[8];
            *(float4*)&bv[0] = *(const float4*)&Ws[kk][tx * 4];
            *(float4*)&bv[4] = *(const float4*)&Ws[kk][128 + tx * 4];
#pragma unroll
            for (int a = 0; a < 4; a++) {
                float av = Hs[ty * 4 + a][kk];
#pragma unroll
                for (int b = 0; b < 8; b++) acc[a][b] += av * bv[b];
            }
        }
        __syncthreads();
    }

    float* out = g_Wh[r];
#pragma unroll
    for (int a = 0; a < 4; a++) {
        int i = i0 + ty * 4 + a;
        *(float4*)&out[(size_t)i * DD + tx * 4] =
            make_float4(acc[a][0], acc[a][1], acc[a][2], acc[a][3]);
        *(float4*)&out[(size_t)i * DD + 128 + tx * 4] =
            make_float4(acc[a][4], acc[a][5], acc[a][6], acc[a][7]);
    }
}

// ---------------------------------------------------------------------------
// Kernel 1b: transpose+convert  g_WhT[r][d][i] = (half)g_Wh[r][i][d]
// ---------------------------------------------------------------------------
__global__ void __launch_bounds__(256) transpose_kernel()
{
    const int r  = blockIdx.z;
    const int i0 = blockIdx.x * 32;
    const int d0 = blockIdx.y * 32;
    __shared__ float t[32][33];

    const int tid = threadIdx.x;
    const int row = tid >> 3;
    const int q   = tid & 7;

    float4 v = *(const float4*)(g_Wh[r] + (size_t)(i0 + row) * DD + d0 + q * 4);
    t[row][q * 4 + 0] = v.x; t[row][q * 4 + 1] = v.y;
    t[row][q * 4 + 2] = v.z; t[row][q * 4 + 3] = v.w;
    __syncthreads();

    uint32_t u0, u1;
    {
        __half h0 = __float2half_rn(t[q * 4 + 0][row]);
        __half h1 = __float2half_rn(t[q * 4 + 1][row]);
        __half h2 = __float2half_rn(t[q * 4 + 2][row]);
        __half h3 = __float2half_rn(t[q * 4 + 3][row]);
        u0 = (uint32_t)__half_as_ushort(h0) | ((uint32_t)__half_as_ushort(h1) << 16);
        u1 = (uint32_t)__half_as_ushort(h2) | ((uint32_t)__half_as_ushort(h3) << 16);
    }
    *(uint2*)&g_WhT[r][(size_t)(d0 + row) * NN + i0 + q * 4] = make_uint2(u0, u1);
}

// ---------------------------------------------------------------------------
// Kernel 2: src/dst projections + factorized-exp packs
// ---------------------------------------------------------------------------
__global__ void __launch_bounds__(256) srcdst_kernel(
    const float* __restrict__ a1, const float* __restrict__ a2,
    const float* __restrict__ a3)
{
    int gw = (blockIdx.x * 256 + threadIdx.x) >> 5;
    int lane = threadIdx.x & 31;
    int r = gw >> 12;
    int i = gw & (NN - 1);
    const float* __restrict__ av = (r == 0) ? a1 : ((r == 1) ? a2 : a3);
    const float* __restrict__ wh = g_Wh[r] + (size_t)i * DD;

    float s = 0.f, d = 0.f;
#pragma unroll
    for (int t = 0; t < 8; t++) {
        float w = wh[lane + 32 * t];
        s += w * av[lane + 32 * t];
        d += w * av[DD + lane + 32 * t];
    }
#pragma unroll
    for (int off = 16; off; off >>= 1) {
        s += __shfl_xor_sync(0xffffffffu, s, off);
        d += __shfl_xor_sync(0xffffffffu, d, off);
    }
    if (lane == 0) {
        g_ip[r][i] = make_float4(s, expf(s), expf(0.2f * s), 0.f);
        g_jp[r][i] = make_float4(d, expf(d), expf(0.2f * d), 0.f);
    }
}

// ---------------------------------------------------------------------------
// Kernel 3: pass-B on mma.sync.  R9 skeleton (2 CTAs/SM, build->sync->mma),
// BK=64 chunks with a 2-stage cp.async ring and single P buffer: half the
// barriers/issue overhead per byte, same prefetch coverage (stage c+1 lands
// during the full build+mma of chunk c).
// CTA tile = 256 d x 64 i, 256 threads, 8 warps = 4 d-groups x 2 i-groups
// (warp tile 64d x 32i), grid 64x3 = 192 CTAs (one wave).
//   C[d][i] = sum_j WhT[d][j] * P[i][j];  out3T[r][d][i] = C[d][i]/l_i
//   P[i][j] = A_ij * (s>0 ? E1_i*F1_j : E2_i*F2_j),  s = src_i + dst_j
// ---------------------------------------------------------------------------
#define SO_WH(s)  ((s) * 36864)            // 2 x (256 rows x 144B) = 73728
#define SO_JP(s)  (73728 + (s) * 1024)     // 2 x 1024 -> 75776
#define SO_P      75776                    // 64 rows x 144B = 9216 -> 84992
#define SO_L      84992                    // float[64]
#define SMEM_PB   85248

__global__ void __launch_bounds__(256, 2) passb_mma_kernel(
    const int* __restrict__ A1, const int* __restrict__ A2,
    const int* __restrict__ A3)
{
    extern __shared__ char smem[];
    const uint32_t sb = smem_u32(smem);
    const int r = blockIdx.y;
    const int* __restrict__ A = (r == 0) ? A1 : ((r == 1) ? A2 : A3);
    const int i0 = blockIdx.x * BI;
    const __half*  __restrict__ WhT = g_WhT[r];
    const float4*  __restrict__ jp  = g_jp[r];

    const int tid  = threadIdx.x;
    const int w    = tid >> 5;
    const int lane = tid & 31;

    float* s_l = (float*)(smem + SO_L);

    // P-build mapping: thread -> row pi = tid>>2, 16 j's at offset (tid&3)*16
    const int pi  = tid >> 2;          // 0..63
    const int pjq = tid & 3;           // 0..3 -> j offset pjq*16
    float4 ipv = g_ip[r][i0 + pi];
    const float src_i = ipv.x, E1 = ipv.y, E2 = ipv.z;
    float l_acc = 0.f;
    const int* arow = A + (size_t)(i0 + pi) * NN + pjq * 16;

    // Wh cp.async mapping: 2048 16B-items over 256 threads -> 8 per thread
    // item idx = tid + 256*t: row = idx>>3 (0..255), piece = idx&7
    const int whr = tid >> 3, whp = tid & 7;

    // warp tile: d-base = (w>>1)*64 (4 groups), i-base = (w&1)*32 (2 groups)
    const int dwb = (w >> 1) * 64;
    const int nwb = (w & 1) * 32;

    // ldmatrix per-lane base offsets (bytes); smem row stride = 144 B
    const int ltile = lane >> 3, lwi = lane & 7;
    const uint32_t a_off =
        (uint32_t)(dwb + (ltile & 1) * 8 + lwi) * WROW + (ltile >> 1) * 16;
    const uint32_t b_off0 =
        (uint32_t)(nwb + ((ltile >> 1)) * 8 + lwi) * WROW + (ltile & 1) * 16;
    const uint32_t b_off1 =
        (uint32_t)(nwb + (2 + (ltile >> 1)) * 8 + lwi) * WROW + (ltile & 1) * 16;

    float c[4][4][4];
#pragma unroll
    for (int mi = 0; mi < 4; mi++)
#pragma unroll
        for (int ni = 0; ni < 4; ni++)
#pragma unroll
            for (int e = 0; e < 4; e++) c[mi][ni][e] = 0.f;

#define ISSUE_CHUNK(cc)                                                        \
    {                                                                          \
        const int j0_ = (cc) * BK;                                             \
        const int st_ = (cc) & 1;                                              \
        _Pragma("unroll")                                                      \
        for (int t = 0; t < 8; t++) {                                          \
            cp16(sb + SO_WH(st_) + (whr + t * 32) * WROW + whp * 16,           \
                 WhT + (size_t)(whr + t * 32) * NN + j0_ + whp * 8);           \
        }                                                                      \
        if (tid < 64) cp16(sb + SO_JP(st_) + tid * 16, jp + j0_ + tid);        \
        CP_COMMIT();                                                           \
    }

    // prologue: stage 0 in flight
    ISSUE_CHUNK(0);

    for (int cch = 0; cch < NCH; cch++) {
        const int st = cch & 1;
        __syncthreads();   // all warps done mma(cch-1): stage st & P free

        if (cch + 1 < NCH) ISSUE_CHUNK(cch + 1) else CP_COMMIT();
        CP_WAIT1();        // stage cch arrived (only cch+1 may remain in flight)
        __syncthreads();   // stage cch visible to all

        // ---- build P(cch): 16 halves per thread ----
        {
            int4 aa0 = *(const int4*)(arow + cch * BK);
            int4 aa1 = *(const int4*)(arow + cch * BK + 4);
            int4 aa2 = *(const int4*)(arow + cch * BK + 8);
            int4 aa3 = *(const int4*)(arow + cch * BK + 12);
            int aav[16] = {aa0.x, aa0.y, aa0.z, aa0.w, aa1.x, aa1.y, aa1.z, aa1.w,
                           aa2.x, aa2.y, aa2.z, aa2.w, aa3.x, aa3.y, aa3.z, aa3.w};
            __half hh[16];
#pragma unroll
            for (int e = 0; e < 16; e++) {
                float4 jv = *(const float4*)(smem + SO_JP(st) + pjq * 256 + e * 16);
                float s = src_i + jv.x;
                float p = (s > 0.f) ? (E1 * jv.y) : (E2 * jv.z);
                p = aav[e] ? p : 0.f;
                hh[e] = __float2half_rn(p);
                l_acc += __half2float(hh[e]);
            }
#pragma unroll
            for (int h = 0; h < 2; h++) {
                uint4 pu;
                pu.x = (uint32_t)__half_as_ushort(hh[h * 8 + 0]) |
                       ((uint32_t)__half_as_ushort(hh[h * 8 + 1]) << 16);
                pu.y = (uint32_t)__half_as_ushort(hh[h * 8 + 2]) |
                       ((uint32_t)__half_as_ushort(hh[h * 8 + 3]) << 16);
                pu.z = (uint32_t)__half_as_ushort(hh[h * 8 + 4]) |
                       ((uint32_t)__half_as_ushort(hh[h * 8 + 5]) << 16);
                pu.w = (uint32_t)__half_as_ushort(hh[h * 8 + 6]) |
                       ((uint32_t)__half_as_ushort(hh[h * 8 + 7]) << 16);
                *(uint4*)(smem + SO_P + pi * WROW + pjq * 32 + h * 16) = pu;
            }
        }
        __syncthreads();   // P(cch) published

        // ---- mma(cch): warp tile 64d x 32i, K=64 in 4 kt steps ----
        {
            const uint32_t whs = sb + SO_WH(st);
            const uint32_t ps  = sb + SO_P;
#pragma unroll
            for (int kt = 0; kt < 4; kt++) {
                uint32_t af[4][4], bf[4][2];
                LDM4(bf[0][0], bf[0][1], bf[1][0], bf[1][1],
                     ps + b_off0 + kt * 32);
                LDM4(bf[2][0], bf[2][1], bf[3][0], bf[3][1],
                     ps + b_off1 + kt * 32);
#pragma unroll
                for (int mi = 0; mi < 4; mi++)
                    LDM4(af[mi][0], af[mi][1], af[mi][2], af[mi][3],
                         whs + a_off + mi * (16 * WROW) + kt * 32);
#pragma unroll
                for (int ni = 0; ni < 4; ni++)
#pragma unroll
                    for (int mi = 0; mi < 4; mi++) {
                        asm volatile(
                            "mma.sync.aligned.m16n8k16.row.col.f32.f16.f16.f32 "
                            "{%0,%1,%2,%3}, {%4,%5,%6,%7}, {%8,%9}, {%0,%1,%2,%3};"
                            : "+f"(c[mi][ni][0]), "+f"(c[mi][ni][1]),
                              "+f"(c[mi][ni][2]), "+f"(c[mi][ni][3])
                            : "r"(af[mi][0]), "r"(af[mi][1]),
                              "r"(af[mi][2]), "r"(af[mi][3]),
                              "r"(bf[ni][0]), "r"(bf[ni][1]));
                    }
            }
        }
    }

    // ---- row sums -> 1/l (4 threads per i-row) ----
    l_acc += __shfl_xor_sync(0xffffffffu, l_acc, 1);
    l_acc += __shfl_xor_sync(0xffffffffu, l_acc, 2);
    __syncthreads();
    if ((tid & 3) == 0) s_l[pi] = l_acc;
    __syncthreads();
    if (tid < BI) {
        float l = s_l[tid];
        s_l[tid] = (l > 0.f) ? (1.f / l) : 0.f;
    }
    __syncthreads();

    // ---- epilogue: scaled stores to transposed partials out3T[d][i] ----
    float* T = g_out3[r];
#pragma unroll
    for (int ni = 0; ni < 4; ni++) {
        int icol = nwb + ni * 8 + (lane & 3) * 2;
        float iv0 = s_l[icol];
        float iv1 = s_l[icol + 1];
#pragma unroll
        for (int mi = 0; mi < 4; mi++) {
            int d = dwb + mi * 16 + (lane >> 2);
            *(float2*)&T[(size_t)d * NN + i0 + icol] =
                make_float2(c[mi][ni][0] * iv0, c[mi][ni][1] * iv1);
            *(float2*)&T[(size_t)(d + 8) * NN + i0 + icol] =
                make_float2(c[mi][ni][2] * iv0, c[mi][ni][3] * iv1);
        }
    }
}

// ---------------------------------------------------------------------------
// Kernel 4: out[i][d] = sum_r out3T[r][d][i] + bias[d]
// ---------------------------------------------------------------------------
__global__ void __launch_bounds__(256) combine_t_kernel(
    const float* __restrict__ bias, float* __restrict__ out)
{
    const int i0 = blockIdx.x * 32;
    const int d0 = blockIdx.y * 32;
    __shared__ float t[32][33];

    const int tid = threadIdx.x;
    const int ty = tid >> 5;
    const int tx = tid & 31;

#pragma unroll
    for (int s = 0; s < 4; s++) {
        int dl = ty + s * 8;
        size_t off = (size_t)(d0 + dl) * NN + i0 + tx;
        t[dl][tx] = g_out3[0][off] + g_out3[1][off] + g_out3[2][off];
    }
    __syncthreads();

    const int il = tid >> 3;
    const int dq = (tid & 7) * 4;
    float4 b = *(const float4*)&bias[d0 + dq];
    float4 v;
    v.x = t[dq + 0][il] + b.x;
    v.y = t[dq + 1][il] + b.y;
    v.z = t[dq + 2][il] + b.z;
    v.w = t[dq + 3][il] + b.w;
    *(float4*)&out[(size_t)(i0 + il) * DD + d0 + dq] = v;
}

// ---------------------------------------------------------------------------
extern "C" void kernel_launch(void* const* d_in, const int* in_sizes, int n_in,
                              void* d_out, int out_size)
{
    const float* H    = (const float*)d_in[0];
    const float* W1   = (const float*)d_in[1];
    const float* W2   = (const float*)d_in[2];
    const float* W3   = (const float*)d_in[3];
    const float* a1   = (const float*)d_in[4];
    const float* a2   = (const float*)d_in[5];
    const float* a3   = (const float*)d_in[6];
    const float* bias = (const float*)d_in[7];
    const int*   A1   = (const int*)d_in[8];
    const int*   A2   = (const int*)d_in[9];
    const int*   A3   = (const int*)d_in[10];
    float* out = (float*)d_out;

    dim3 wh_grid(NN / 32, 3);
    wh_gemm_kernel<<<wh_grid, 256>>>(H, W1, W2, W3);

    dim3 tr_grid(NN / 32, DD / 32, 3);
    transpose_kernel<<<tr_grid, 256>>>();

    srcdst_kernel<<<3 * NN / 8, 256>>>(a1, a2, a3);

    cudaFuncSetAttribute(passb_mma_kernel,
                         cudaFuncAttributeMaxDynamicSharedMemorySize, SMEM_PB);
    dim3 pb_grid(NN / BI, 3);
    passb_mma_kernel<<<pb_grid, 256, SMEM_PB>>>(A1, A2, A3);

    dim3 cb_grid(NN / 32, DD / 32);
    combine_t_kernel<<<cb_grid, 256>>>(bias, out);
}

// round 14
// speedup vs baseline: 1.2352x; 1.0349x over previous
#include <cuda_runtime.h>
#include <cuda_fp16.h>
#include <math.h>
#include <stdint.h>

#define NN 4096
#define DD 256
#define BI 64      // passb: i-rows per CTA
#define BK 32      // passb: j per chunk
#define NCH (NN / BK)

// ---------------- scratch (device globals; no allocations allowed) ----------
__device__ __half g_WhT[3][DD * NN];     // fp16 Wh transposed [d][j]
__device__ float4 g_ip[3][NN];           // {src, exp(src), exp(.2src), 0}
__device__ float4 g_jp[3][NN];           // {dst, exp(dst), exp(.2dst), 0}
__device__ float  g_out3[3][DD * NN];    // TRANSPOSED partials [d][i]

// ============================ helpers =======================================
__device__ __forceinline__ uint32_t smem_u32(const void* p) {
    uint32_t a;
    asm("{ .reg .u64 t; cvta.to.shared.u64 t, %1; cvt.u32.u64 %0, t; }"
        : "=r"(a) : "l"(p));
    return a;
}
__device__ __forceinline__ void cp16(uint32_t dst, const void* src) {
    asm volatile("cp.async.cg.shared.global [%0], [%1], 16;"
                 :: "r"(dst), "l"(src) : "memory");
}
#define CP_COMMIT() asm volatile("cp.async.commit_group;" ::: "memory")
#define CP_WAIT2()  asm volatile("cp.async.wait_group 2;" ::: "memory")

#define LDM4(r0, r1, r2, r3, addr)                                             \
    asm volatile("ldmatrix.sync.aligned.m8n8.x4.shared.b16 {%0,%1,%2,%3}, [%4];" \
                 : "=r"(r0), "=r"(r1), "=r"(r2), "=r"(r3) : "r"(addr))

// ---------------------------------------------------------------------------
// Kernel 1 (FUSED): Wh = H @ W^T, then in-register:
//   - src/dst projections + factorized exp packs
//   - fp16 transposed store to g_WhT
// fp32 Wh never touches DRAM.
// ---------------------------------------------------------------------------
__global__ void __launch_bounds__(256) wh_fused_kernel(
    const float* __restrict__ H,
    const float* __restrict__ W1, const float* __restrict__ W2,
    const float* __restrict__ W3,
    const float* __restrict__ a1, const float* __restrict__ a2,
    const float* __restrict__ a3)
{
    const int r = blockIdx.y;
    const float* __restrict__ W  = (r == 0) ? W1 : ((r == 1) ? W2 : W3);
    const float* __restrict__ av = (r == 0) ? a1 : ((r == 1) ? a2 : a3);
    const int i0 = blockIdx.x * 32;

    __shared__ float pool[9216];          // 36864 B, multi-purpose
    float* Hs = pool;                     // [32][32]
    float* Ws = pool + 1024;              // [32][256]
    __half* tT = (__half*)pool;           // [256][40] halves (reused after GEMM)

    const int tid = threadIdx.x;
    const int ty = tid >> 5;
    const int tx = tid & 31;

    float acc[4][8];
#pragma unroll
    for (int a = 0; a < 4; a++)
#pragma unroll
        for (int b = 0; b < 8; b++) acc[a][b] = 0.f;

    for (int k0 = 0; k0 < DD; k0 += 32) {
        {
            int row = tid >> 3, q = tid & 7;
            float4 v = *(const float4*)(H + (size_t)(i0 + row) * DD + k0 + q * 4);
            Hs[row * 32 + q * 4 + 0] = v.x; Hs[row * 32 + q * 4 + 1] = v.y;
            Hs[row * 32 + q * 4 + 2] = v.z; Hs[row * 32 + q * 4 + 3] = v.w;
        }
        {
            const float* wp = W + (size_t)tid * DD + k0;
#pragma unroll
            for (int q = 0; q < 8; q++) {
                float4 v = *(const float4*)(wp + q * 4);
                Ws[(q * 4 + 0) * 256 + tid] = v.x; Ws[(q * 4 + 1) * 256 + tid] = v.y;
                Ws[(q * 4 + 2) * 256 + tid] = v.z; Ws[(q * 4 + 3) * 256 + tid] = v.w;
            }
        }
        __syncthreads();
#pragma unroll
        for (int kk = 0; kk < 32; kk++) {
            float bv[8];
            *(float4*)&bv[0] = *(const float4*)&Ws[kk * 256 + tx * 4];
            *(float4*)&bv[4] = *(const float4*)&Ws[kk * 256 + 128 + tx * 4];
#pragma unroll
            for (int a = 0; a < 4; a++) {
                float avv = Hs[(ty * 4 + a) * 32 + kk];
#pragma unroll
                for (int b = 0; b < 8; b++) acc[a][b] += avv * bv[b];
            }
        }
        __syncthreads();
    }

    // ---- fused src/dst: per-warp dot with a[:256] / a[256:512] ----
    {
        float sp[4] = {0.f, 0.f, 0.f, 0.f};
        float dp[4] = {0.f, 0.f, 0.f, 0.f};
#pragma unroll
        for (int b = 0; b < 8; b++) {
            int col = (b < 4) ? (tx * 4 + b) : (128 + tx * 4 + (b - 4));
            float a_s = av[col];
            float a_d = av[DD + col];
#pragma unroll
            for (int a = 0; a < 4; a++) {
                sp[a] += acc[a][b] * a_s;
                dp[a] += acc[a][b] * a_d;
            }
        }
#pragma unroll
        for (int off = 16; off; off >>= 1) {
#pragma unroll
            for (int a = 0; a < 4; a++) {
                sp[a] += __shfl_xor_sync(0xffffffffu, sp[a], off);
                dp[a] += __shfl_xor_sync(0xffffffffu, dp[a], off);
            }
        }
        if (tx == 0) {
#pragma unroll
            for (int a = 0; a < 4; a++) {
                int i = i0 + ty * 4 + a;
                g_ip[r][i] = make_float4(sp[a], expf(sp[a]), expf(0.2f * sp[a]), 0.f);
                g_jp[r][i] = make_float4(dp[a], expf(dp[a]), expf(0.2f * dp[a]), 0.f);
            }
        }
    }

    // ---- fused transpose: stage fp16 [d][i] tile (stride 40 halves = 80 B,
    // 16B-aligned rows), then 4x uint4 per thread to g_WhT ----
#pragma unroll
    for (int b = 0; b < 8; b++) {
        int col = (b < 4) ? (tx * 4 + b) : (128 + tx * 4 + (b - 4));
#pragma unroll
        for (int k = 0; k < 2; k++) {
            __half2 v = __floats2half2_rn(acc[2 * k][b], acc[2 * k + 1][b]);
            *(__half2*)&tT[col * 40 + ty * 4 + 2 * k] = v;
        }
    }
    __syncthreads();
    {
        const int d = tid;                               // 0..255
        const uint4* srcp = (const uint4*)&tT[d * 40];   // 80B base, 16B aligned
        uint4 u[4];
#pragma unroll
        for (int q = 0; q < 4; q++) u[q] = srcp[q];      // halves q*8 .. q*8+7
        uint4* dst = (uint4*)&g_WhT[r][(size_t)d * NN + i0];
#pragma unroll
        for (int q = 0; q < 4; q++) dst[q] = u[q];
    }
}

// ---------------------------------------------------------------------------
// Kernel 2: pass-B on mma.sync (VERBATIM R9 winner: 4-stage cp.async ring,
// A prefetched in regs, build->sync->mma, 2 CTAs/SM, grid 64x3 one wave).
// CTA tile = 256 d x 64 i, 8 warps = 4 d-groups x 2 i-groups (64d x 32i each).
//   C[d][i] = sum_j WhT[d][j] * P[i][j];  out3T[r][d][i] = C[d][i]/l_i
//   P[i][j] = A_ij * (s>0 ? E1_i*F1_j : E2_i*F2_j),  s = src_i + dst_j
// ---------------------------------------------------------------------------
#define SO_WH(s)  ((s) * 20480)            // 4 x (256 rows x 80B) = 81920
#define SO_JP(s)  (81920 + (s) * 512)      // 4 x 512 -> 83968
#define SO_P(b)   (83968 + (b) * 5120)     // 2 x (64 rows x 80B) -> 94208
#define SO_L      94208                    // float[64]
#define SMEM_PB   94464

__global__ void __launch_bounds__(256, 2) passb_mma_kernel(
    const int* __restrict__ A1, const int* __restrict__ A2,
    const int* __restrict__ A3)
{
    extern __shared__ char smem[];
    const uint32_t sb = smem_u32(smem);
    const int r = blockIdx.y;
    const int* __restrict__ A = (r == 0) ? A1 : ((r == 1) ? A2 : A3);
    const int i0 = blockIdx.x * BI;
    const __half*  __restrict__ WhT = g_WhT[r];
    const float4*  __restrict__ jp  = g_jp[r];

    const int tid  = threadIdx.x;
    const int w    = tid >> 5;
    const int lane = tid & 31;

    float* s_l = (float*)(smem + SO_L);

    // P-build mapping: thread -> row pi = tid>>2, 8 j's at offset (tid&3)*8
    const int pi  = tid >> 2;          // 0..63
    const int pjq = tid & 3;           // 0..3 -> j offset pjq*8
    float4 ip = g_ip[r][i0 + pi];
    const float src_i = ip.x, E1 = ip.y, E2 = ip.z;
    float l_acc = 0.f;
    const int* arow = A + (size_t)(i0 + pi) * NN + pjq * 8;

    // Wh cp.async mapping: 1024 16B-items over 256 threads -> 4 per thread
    const int whr = tid >> 2, whp = tid & 3;

    // warp tile: d-base = (w>>1)*64 (4 groups), i-base = (w&1)*32 (2 groups)
    const int dwb = (w >> 1) * 64;
    const int nwb = (w & 1) * 32;

    // ldmatrix per-lane base offsets (bytes); smem row stride = 80 B
    const int ltile = lane >> 3, lwi = lane & 7;
    const uint32_t a_off =
        (uint32_t)(dwb + (ltile & 1) * 8 + lwi) * 80 + (ltile >> 1) * 16;
    const uint32_t b_off0 =
        (uint32_t)(nwb + ((ltile >> 1)) * 8 + lwi) * 80 + (ltile & 1) * 16;
    const uint32_t b_off1 =
        (uint32_t)(nwb + (2 + (ltile >> 1)) * 8 + lwi) * 80 + (ltile & 1) * 16;

    float c[4][4][4];
#pragma unroll
    for (int mi = 0; mi < 4; mi++)
#pragma unroll
        for (int ni = 0; ni < 4; ni++)
#pragma unroll
            for (int e = 0; e < 4; e++) c[mi][ni][e] = 0.f;

#define ISSUE_CHUNK(cc)                                                        \
    {                                                                          \
        const int j0_ = (cc) * BK;                                             \
        const int st_ = (cc) & 3;                                              \
        _Pragma("unroll")                                                      \
        for (int t = 0; t < 4; t++) {                                          \
            cp16(sb + SO_WH(st_) + (whr + t * 64) * 80 + whp * 16,             \
                 WhT + (size_t)(whr + t * 64) * NN + j0_ + whp * 8);           \
        }                                                                      \
        if (tid < 32) cp16(sb + SO_JP(st_) + tid * 16, jp + j0_ + tid);        \
        CP_COMMIT();                                                           \
    }

    // prologue: stages 0,1,2 in flight; A chunk 0 in regs
    ISSUE_CHUNK(0); ISSUE_CHUNK(1); ISSUE_CHUNK(2);
    int4 aa0 = *(const int4*)arow;
    int4 aa1 = *(const int4*)(arow + 4);

    for (int cch = 0; cch < NCH; cch++) {
        const int st = cch & 3;
        const int pb = cch & 1;
        CP_WAIT2();
        __syncthreads();   // stage-cch data visible; all warps done mma(cch-1)

        if (cch + 3 < NCH) ISSUE_CHUNK(cch + 3) else CP_COMMIT();

        int4 aan0 = aa0, aan1 = aa1;
        if (cch + 1 < NCH) {
            aan0 = *(const int4*)(arow + (cch + 1) * BK);
            aan1 = *(const int4*)(arow + (cch + 1) * BK + 4);
        }

        // ---- build P(cch): 8 halves per thread ----
        {
            int aav[8] = {aa0.x, aa0.y, aa0.z, aa0.w, aa1.x, aa1.y, aa1.z, aa1.w};
            __half hh[8];
#pragma unroll
            for (int e = 0; e < 8; e++) {
                float4 jv = *(const float4*)(smem + SO_JP(st) + pjq * 128 + e * 16);
                float s = src_i + jv.x;
                float p = (s > 0.f) ? (E1 * jv.y) : (E2 * jv.z);
                p = aav[e] ? p : 0.f;
                hh[e] = __float2half_rn(p);
                l_acc += __half2float(hh[e]);
            }
            uint4 pu;
            pu.x = (uint32_t)__half_as_ushort(hh[0]) |
                   ((uint32_t)__half_as_ushort(hh[1]) << 16);
            pu.y = (uint32_t)__half_as_ushort(hh[2]) |
                   ((uint32_t)__half_as_ushort(hh[3]) << 16);
            pu.z = (uint32_t)__half_as_ushort(hh[4]) |
                   ((uint32_t)__half_as_ushort(hh[5]) << 16);
            pu.w = (uint32_t)__half_as_ushort(hh[6]) |
                   ((uint32_t)__half_as_ushort(hh[7]) << 16);
            *(uint4*)(smem + SO_P(pb) + pi * 80 + pjq * 16) = pu;
        }
        aa0 = aan0; aa1 = aan1;
        __syncthreads();

        // ---- mma(cch): warp tile 64d x 32i ----
        {
            const uint32_t whs = sb + SO_WH(st);
            const uint32_t ps  = sb + SO_P(pb);
#pragma unroll
            for (int kt = 0; kt < 2; kt++) {
                uint32_t af[4][4], bf[4][2];
                LDM4(bf[0][0], bf[0][1], bf[1][0], bf[1][1],
                     ps + b_off0 + kt * 32);
                LDM4(bf[2][0], bf[2][1], bf[3][0], bf[3][1],
                     ps + b_off1 + kt * 32);
#pragma unroll
                for (int mi = 0; mi < 4; mi++)
                    LDM4(af[mi][0], af[mi][1], af[mi][2], af[mi][3],
                         whs + a_off + mi * 1280 + kt * 32);
#pragma unroll
                for (int ni = 0; ni < 4; ni++)
#pragma unroll
                    for (int mi = 0; mi < 4; mi++) {
                        asm volatile(
                            "mma.sync.aligned.m16n8k16.row.col.f32.f16.f16.f32 "
                            "{%0,%1,%2,%3}, {%4,%5,%6,%7}, {%8,%9}, {%0,%1,%2,%3};"
                            : "+f"(c[mi][ni][0]), "+f"(c[mi][ni][1]),
                              "+f"(c[mi][ni][2]), "+f"(c[mi][ni][3])
                            : "r"(af[mi][0]), "r"(af[mi][1]),
                              "r"(af[mi][2]), "r"(af[mi][3]),
                              "r"(bf[ni][0]), "r"(bf[ni][1]));
                    }
            }
        }
    }

    // ---- row sums -> 1/l (4 threads per i-row) ----
    l_acc += __shfl_xor_sync(0xffffffffu, l_acc, 1);
    l_acc += __shfl_xor_sync(0xffffffffu, l_acc, 2);
    __syncthreads();
    if ((tid & 3) == 0) s_l[pi] = l_acc;
    __syncthreads();
    if (tid < BI) {
        float l = s_l[tid];
        s_l[tid] = (l > 0.f) ? (1.f / l) : 0.f;
    }
    __syncthreads();

    // ---- epilogue: scaled stores to transposed partials out3T[d][i] ----
    float* T = g_out3[r];
#pragma unroll
    for (int ni = 0; ni < 4; ni++) {
        int icol = nwb + ni * 8 + (lane & 3) * 2;
        float iv0 = s_l[icol];
        float iv1 = s_l[icol + 1];
#pragma unroll
        for (int mi = 0; mi < 4; mi++) {
            int d = dwb + mi * 16 + (lane >> 2);
            *(float2*)&T[(size_t)d * NN + i0 + icol] =
                make_float2(c[mi][ni][0] * iv0, c[mi][ni][1] * iv1);
            *(float2*)&T[(size_t)(d + 8) * NN + i0 + icol] =
                make_float2(c[mi][ni][2] * iv0, c[mi][ni][3] * iv1);
        }
    }
}

// ---------------------------------------------------------------------------
// Kernel 3: out[i][d] = sum_r out3T[r][d][i] + bias[d]
// ---------------------------------------------------------------------------
__global__ void __launch_bounds__(256) combine_t_kernel(
    const float* __restrict__ bias, float* __restrict__ out)
{
    const int i0 = blockIdx.x * 32;
    const int d0 = blockIdx.y * 32;
    __shared__ float t[32][33];

    const int tid = threadIdx.x;
    const int ty = tid >> 5;
    const int tx = tid & 31;

#pragma unroll
    for (int s = 0; s < 4; s++) {
        int dl = ty + s * 8;
        size_t off = (size_t)(d0 + dl) * NN + i0 + tx;
        t[dl][tx] = g_out3[0][off] + g_out3[1][off] + g_out3[2][off];
    }
    __syncthreads();

    const int il = tid >> 3;
    const int dq = (tid & 7) * 4;
    float4 b = *(const float4*)&bias[d0 + dq];
    float4 v;
    v.x = t[dq + 0][il] + b.x;
    v.y = t[dq + 1][il] + b.y;
    v.z = t[dq + 2][il] + b.z;
    v.w = t[dq + 3][il] + b.w;
    *(float4*)&out[(size_t)(i0 + il) * DD + d0 + dq] = v;
}

// ---------------------------------------------------------------------------
extern "C" void kernel_launch(void* const* d_in, const int* in_sizes, int n_in,
                              void* d_out, int out_size)
{
    const float* H    = (const float*)d_in[0];
    const float* W1   = (const float*)d_in[1];
    const float* W2   = (const float*)d_in[2];
    const float* W3   = (const float*)d_in[3];
    const float* a1   = (const float*)d_in[4];
    const float* a2   = (const float*)d_in[5];
    const float* a3   = (const float*)d_in[6];
    const float* bias = (const float*)d_in[7];
    const int*   A1   = (const int*)d_in[8];
    const int*   A2   = (const int*)d_in[9];
    const int*   A3   = (const int*)d_in[10];
    float* out = (float*)d_out;

    dim3 wh_grid(NN / 32, 3);
    wh_fused_kernel<<<wh_grid, 256>>>(H, W1, W2, W3, a1, a2, a3);

    cudaFuncSetAttribute(passb_mma_kernel,
                         cudaFuncAttributeMaxDynamicSharedMemorySize, SMEM_PB);
    dim3 pb_grid(NN / BI, 3);
    passb_mma_kernel<<<pb_grid, 256, SMEM_PB>>>(A1, A2, A3);

    dim3 cb_grid(NN / 32, DD / 32);
    combine_t_kernel<<<cb_grid, 256>>>(bias, out);
}

// round 16
// speedup vs baseline: 1.3966x; 1.1307x over previous
#include <cuda_runtime.h>
#include <cuda_fp16.h>
#include <math.h>
#include <stdint.h>

#define NN 4096
#define DD 256
#define BI 64      // passb: i-rows per CTA
#define BK 32      // passb: j per chunk
#define NCH (NN / BK)

// ---------------- scratch (device globals; no allocations allowed) ----------
__device__ __half g_WhT[3][DD * NN];     // fp16 Wh transposed [d][j]
__device__ float4 g_ip[3][NN];           // {src, exp(src), exp(.2src), 0}
__device__ float4 g_jp[3][NN];           // {dst, exp(dst), exp(.2dst), 0}
__device__ float  g_out3[3][DD * NN];    // TRANSPOSED partials [d][i]

// ============================ helpers =======================================
__device__ __forceinline__ uint32_t smem_u32(const void* p) {
    uint32_t a;
    asm("{ .reg .u64 t; cvta.to.shared.u64 t, %1; cvt.u32.u64 %0, t; }"
        : "=r"(a) : "l"(p));
    return a;
}
__device__ __forceinline__ void cp16(uint32_t dst, const void* src) {
    asm volatile("cp.async.cg.shared.global [%0], [%1], 16;"
                 :: "r"(dst), "l"(src) : "memory");
}
#define CP_COMMIT() asm volatile("cp.async.commit_group;" ::: "memory")
#define CP_WAIT2()  asm volatile("cp.async.wait_group 2;" ::: "memory")

#define LDM4(r0, r1, r2, r3, addr)                                             \
    asm volatile("ldmatrix.sync.aligned.m8n8.x4.shared.b16 {%0,%1,%2,%3}, [%4];" \
                 : "=r"(r0), "=r"(r1), "=r"(r2), "=r"(r3) : "r"(addr))

#define MMA16816(c0, c1, c2, c3, a0, a1, a2, a3, b0, b1)                       \
    asm volatile(                                                              \
        "mma.sync.aligned.m16n8k16.row.col.f32.f16.f16.f32 "                   \
        "{%0,%1,%2,%3}, {%4,%5,%6,%7}, {%8,%9}, {%0,%1,%2,%3};"                \
        : "+f"(c0), "+f"(c1), "+f"(c2), "+f"(c3)                               \
        : "r"(a0), "r"(a1), "r"(a2), "r"(a3), "r"(b0), "r"(b1))

__device__ __forceinline__ uint32_t h2u(float a, float b) {
    __half2 h = __floats2half2_rn(a, b);
    return *(uint32_t*)&h;
}

// ---------------------------------------------------------------------------
// Kernel 1: whT_mma — tensor-core H@W^T with fused src/dst + fp16 WhT output.
//   C[d][j] = sum_k W[d][k] * H[j][k]  (= Wh[j][d]), fp16 inputs, fp32 accum.
// CTA = 256 d x 64 j, 256 threads, 8 warps (4 d-groups x 2 j-groups, 64dx32j),
// K = 256 in 8 chunks of 32.  Same mma machinery as passb.
// Epilogue: WhT half2 stores; src_j/dst_j = sum_d a[d]*C[d][j] via shuffle +
// smem atomics; exp packs to g_ip/g_jp.
// ---------------------------------------------------------------------------
__global__ void __launch_bounds__(256) whT_mma_kernel(
    const float* __restrict__ H,
    const float* __restrict__ W1, const float* __restrict__ W2,
    const float* __restrict__ W3,
    const float* __restrict__ a1, const float* __restrict__ a2,
    const float* __restrict__ a3)
{
    const int r = blockIdx.y;
    const float* __restrict__ W  = (r == 0) ? W1 : ((r == 1) ? W2 : W3);
    const float* __restrict__ av = (r == 0) ? a1 : ((r == 1) ? a2 : a3);
    const int i0 = blockIdx.x * 64;      // j tile base

    __shared__ __half As[256 * 40];      // W tile  [256 d][32 k], 80B rows
    __shared__ __half Bs[64 * 40];       // H tile  [64 j][32 k],  80B rows
    __shared__ float  s_sp[64], s_dp[64];

    const int tid  = threadIdx.x;
    const int w    = tid >> 5;
    const int lane = tid & 31;

    if (tid < 64) { s_sp[tid] = 0.f; s_dp[tid] = 0.f; }

    const int dwb = (w >> 1) * 64;
    const int nwb = (w & 1) * 32;
    const int ltile = lane >> 3, lwi = lane & 7;
    const uint32_t sbA = smem_u32(As);
    const uint32_t sbB = smem_u32(Bs);
    const uint32_t a_off =
        (uint32_t)(dwb + (ltile & 1) * 8 + lwi) * 80 + (ltile >> 1) * 16;
    const uint32_t b_off0 =
        (uint32_t)(nwb + ((ltile >> 1)) * 8 + lwi) * 80 + (ltile & 1) * 16;
    const uint32_t b_off1 =
        (uint32_t)(nwb + (2 + (ltile >> 1)) * 8 + lwi) * 80 + (ltile & 1) * 16;

    float c[4][4][4];
#pragma unroll
    for (int mi = 0; mi < 4; mi++)
#pragma unroll
        for (int ni = 0; ni < 4; ni++)
#pragma unroll
            for (int e = 0; e < 4; e++) c[mi][ni][e] = 0.f;

    const int hrow = tid >> 2;           // 0..63
    const int hpart = tid & 3;           // 0..3 -> 8 floats each

    for (int cch = 0; cch < 8; cch++) {
        const int k0 = cch * 32;
        __syncthreads();   // prev mma done reading tiles

        // ---- build W tile: thread = row d = tid, 32 floats -> 32 halves ----
        {
            const float* wp = W + (size_t)tid * DD + k0;
            float4 v0 = *(const float4*)(wp + 0);
            float4 v1 = *(const float4*)(wp + 4);
            float4 v2 = *(const float4*)(wp + 8);
            float4 v3 = *(const float4*)(wp + 12);
            float4 v4 = *(const float4*)(wp + 16);
            float4 v5 = *(const float4*)(wp + 20);
            float4 v6 = *(const float4*)(wp + 24);
            float4 v7 = *(const float4*)(wp + 28);
            uint4* dst = (uint4*)&As[tid * 40];
            dst[0] = make_uint4(h2u(v0.x, v0.y), h2u(v0.z, v0.w),
                                h2u(v1.x, v1.y), h2u(v1.z, v1.w));
            dst[1] = make_uint4(h2u(v2.x, v2.y), h2u(v2.z, v2.w),
                                h2u(v3.x, v3.y), h2u(v3.z, v3.w));
            dst[2] = make_uint4(h2u(v4.x, v4.y), h2u(v4.z, v4.w),
                                h2u(v5.x, v5.y), h2u(v5.z, v5.w));
            dst[3] = make_uint4(h2u(v6.x, v6.y), h2u(v6.z, v6.w),
                                h2u(v7.x, v7.y), h2u(v7.z, v7.w));
        }
        // ---- build H tile: row j = tid>>2, part = tid&3 (8 floats) ----
        {
            const float* hp = H + (size_t)(i0 + hrow) * DD + k0 + hpart * 8;
            float4 v0 = *(const float4*)(hp + 0);
            float4 v1 = *(const float4*)(hp + 4);
            *(uint4*)&Bs[hrow * 40 + hpart * 8] =
                make_uint4(h2u(v0.x, v0.y), h2u(v0.z, v0.w),
                           h2u(v1.x, v1.y), h2u(v1.z, v1.w));
        }
        __syncthreads();   // tiles published

        // ---- mma: identical structure to passb ----
#pragma unroll
        for (int kt = 0; kt < 2; kt++) {
            uint32_t af[4][4], bf[4][2];
            LDM4(bf[0][0], bf[0][1], bf[1][0], bf[1][1], sbB + b_off0 + kt * 32);
            LDM4(bf[2][0], bf[2][1], bf[3][0], bf[3][1], sbB + b_off1 + kt * 32);
#pragma unroll
            for (int mi = 0; mi < 4; mi++)
                LDM4(af[mi][0], af[mi][1], af[mi][2], af[mi][3],
                     sbA + a_off + mi * 1280 + kt * 32);
#pragma unroll
            for (int ni = 0; ni < 4; ni++)
#pragma unroll
                for (int mi = 0; mi < 4; mi++)
                    MMA16816(c[mi][ni][0], c[mi][ni][1], c[mi][ni][2], c[mi][ni][3],
                             af[mi][0], af[mi][1], af[mi][2], af[mi][3],
                             bf[ni][0], bf[ni][1]);
        }
    }

    // ---- epilogue 1: WhT fp16 stores (C[d][j] -> g_WhT[d][i0+j]) ----
    __half* T16 = g_WhT[r];
#pragma unroll
    for (int ni = 0; ni < 4; ni++) {
        int icol = nwb + ni * 8 + (lane & 3) * 2;
#pragma unroll
        for (int mi = 0; mi < 4; mi++) {
            int d = dwb + mi * 16 + (lane >> 2);
            __half2 v0 = __floats2half2_rn(c[mi][ni][0], c[mi][ni][1]);
            __half2 v1 = __floats2half2_rn(c[mi][ni][2], c[mi][ni][3]);
            *(__half2*)&T16[(size_t)d * NN + i0 + icol] = v0;
            *(__half2*)&T16[(size_t)(d + 8) * NN + i0 + icol] = v1;
        }
    }

    // ---- epilogue 2: src/dst partials.  src_j = sum_d a_s[d]*C[d][j] ----
    {
        float asv[4][2], adv[4][2];
#pragma unroll
        for (int mi = 0; mi < 4; mi++) {
            int d = dwb + mi * 16 + (lane >> 2);
            asv[mi][0] = av[d];       asv[mi][1] = av[d + 8];
            adv[mi][0] = av[DD + d];  adv[mi][1] = av[DD + d + 8];
        }
#pragma unroll
        for (int ni = 0; ni < 4; ni++) {
            int icol = nwb + ni * 8 + (lane & 3) * 2;
            float sp0 = 0.f, sp1 = 0.f, dp0 = 0.f, dp1 = 0.f;
#pragma unroll
            for (int mi = 0; mi < 4; mi++) {
                sp0 += asv[mi][0] * c[mi][ni][0] + asv[mi][1] * c[mi][ni][2];
                sp1 += asv[mi][0] * c[mi][ni][1] + asv[mi][1] * c[mi][ni][3];
                dp0 += adv[mi][0] * c[mi][ni][0] + adv[mi][1] * c[mi][ni][2];
                dp1 += adv[mi][0] * c[mi][ni][1] + adv[mi][1] * c[mi][ni][3];
            }
            // reduce over the 8 lanes sharing (lane & 3)
#pragma unroll
            for (int off = 4; off <= 16; off <<= 1) {
                sp0 += __shfl_xor_sync(0xffffffffu, sp0, off);
                sp1 += __shfl_xor_sync(0xffffffffu, sp1, off);
                dp0 += __shfl_xor_sync(0xffffffffu, dp0, off);
                dp1 += __shfl_xor_sync(0xffffffffu, dp1, off);
            }
            if (lane < 4) {
                atomicAdd(&s_sp[icol], sp0);
                atomicAdd(&s_sp[icol + 1], sp1);
                atomicAdd(&s_dp[icol], dp0);
                atomicAdd(&s_dp[icol + 1], dp1);
            }
        }
    }
    __syncthreads();

    // ---- epilogue 3: exp packs ----
    if (tid < 64) {
        int i = i0 + tid;
        float s = s_sp[tid], d = s_dp[tid];
        g_ip[r][i] = make_float4(s, expf(s), expf(0.2f * s), 0.f);
        g_jp[r][i] = make_float4(d, expf(d), expf(0.2f * d), 0.f);
    }
}

// ---------------------------------------------------------------------------
// Kernel 2: pass-B on mma.sync (VERBATIM R9 winner: 4-stage cp.async ring,
// A prefetched in regs, build->sync->mma, 2 CTAs/SM, grid 64x3 one wave).
// CTA tile = 256 d x 64 i, 8 warps = 4 d-groups x 2 i-groups (64d x 32i each).
//   C[d][i] = sum_j WhT[d][j] * P[i][j];  out3T[r][d][i] = C[d][i]/l_i
//   P[i][j] = A_ij * (s>0 ? E1_i*F1_j : E2_i*F2_j),  s = src_i + dst_j
// ---------------------------------------------------------------------------
#define SO_WH(s)  ((s) * 20480)            // 4 x (256 rows x 80B) = 81920
#define SO_JP(s)  (81920 + (s) * 512)      // 4 x 512 -> 83968
#define SO_P(b)   (83968 + (b) * 5120)     // 2 x (64 rows x 80B) -> 94208
#define SO_L      94208                    // float[64]
#define SMEM_PB   94464

__global__ void __launch_bounds__(256, 2) passb_mma_kernel(
    const int* __restrict__ A1, const int* __restrict__ A2,
    const int* __restrict__ A3)
{
    extern __shared__ char smem[];
    const uint32_t sb = smem_u32(smem);
    const int r = blockIdx.y;
    const int* __restrict__ A = (r == 0) ? A1 : ((r == 1) ? A2 : A3);
    const int i0 = blockIdx.x * BI;
    const __half*  __restrict__ WhT = g_WhT[r];
    const float4*  __restrict__ jp  = g_jp[r];

    const int tid  = threadIdx.x;
    const int w    = tid >> 5;
    const int lane = tid & 31;

    float* s_l = (float*)(smem + SO_L);

    const int pi  = tid >> 2;
    const int pjq = tid & 3;
    float4 ip = g_ip[r][i0 + pi];
    const float src_i = ip.x, E1 = ip.y, E2 = ip.z;
    float l_acc = 0.f;
    const int* arow = A + (size_t)(i0 + pi) * NN + pjq * 8;

    const int whr = tid >> 2, whp = tid & 3;

    const int dwb = (w >> 1) * 64;
    const int nwb = (w & 1) * 32;

    const int ltile = lane >> 3, lwi = lane & 7;
    const uint32_t a_off =
        (uint32_t)(dwb + (ltile & 1) * 8 + lwi) * 80 + (ltile >> 1) * 16;
    const uint32_t b_off0 =
        (uint32_t)(nwb + ((ltile >> 1)) * 8 + lwi) * 80 + (ltile & 1) * 16;
    const uint32_t b_off1 =
        (uint32_t)(nwb + (2 + (ltile >> 1)) * 8 + lwi) * 80 + (ltile & 1) * 16;

    float c[4][4][4];
#pragma unroll
    for (int mi = 0; mi < 4; mi++)
#pragma unroll
        for (int ni = 0; ni < 4; ni++)
#pragma unroll
            for (int e = 0; e < 4; e++) c[mi][ni][e] = 0.f;

#define ISSUE_CHUNK(cc)                                                        \
    {                                                                          \
        const int j0_ = (cc) * BK;                                             \
        const int st_ = (cc) & 3;                                              \
        _Pragma("unroll")                                                      \
        for (int t = 0; t < 4; t++) {                                          \
            cp16(sb + SO_WH(st_) + (whr + t * 64) * 80 + whp * 16,             \
                 WhT + (size_t)(whr + t * 64) * NN + j0_ + whp * 8);           \
        }                                                                      \
        if (tid < 32) cp16(sb + SO_JP(st_) + tid * 16, jp + j0_ + tid);        \
        CP_COMMIT();                                                           \
    }

    ISSUE_CHUNK(0); ISSUE_CHUNK(1); ISSUE_CHUNK(2);
    int4 aa0 = *(const int4*)arow;
    int4 aa1 = *(const int4*)(arow + 4);

    for (int cch = 0; cch < NCH; cch++) {
        const int st = cch & 3;
        const int pb = cch & 1;
        CP_WAIT2();
        __syncthreads();

        if (cch + 3 < NCH) ISSUE_CHUNK(cch + 3) else CP_COMMIT();

        int4 aan0 = aa0, aan1 = aa1;
        if (cch + 1 < NCH) {
            aan0 = *(const int4*)(arow + (cch + 1) * BK);
            aan1 = *(const int4*)(arow + (cch + 1) * BK + 4);
        }

        {
            int aav[8] = {aa0.x, aa0.y, aa0.z, aa0.w, aa1.x, aa1.y, aa1.z, aa1.w};
            __half hh[8];
#pragma unroll
            for (int e = 0; e < 8; e++) {
                float4 jv = *(const float4*)(smem + SO_JP(st) + pjq * 128 + e * 16);
                float s = src_i + jv.x;
                float p = (s > 0.f) ? (E1 * jv.y) : (E2 * jv.z);
                p = aav[e] ? p : 0.f;
                hh[e] = __float2half_rn(p);
                l_acc += __half2float(hh[e]);
            }
            uint4 pu;
            pu.x = (uint32_t)__half_as_ushort(hh[0]) |
                   ((uint32_t)__half_as_ushort(hh[1]) << 16);
            pu.y = (uint32_t)__half_as_ushort(hh[2]) |
                   ((uint32_t)__half_as_ushort(hh[3]) << 16);
            pu.z = (uint32_t)__half_as_ushort(hh[4]) |
                   ((uint32_t)__half_as_ushort(hh[5]) << 16);
            pu.w = (uint32_t)__half_as_ushort(hh[6]) |
                   ((uint32_t)__half_as_ushort(hh[7]) << 16);
            *(uint4*)(smem + SO_P(pb) + pi * 80 + pjq * 16) = pu;
        }
        aa0 = aan0; aa1 = aan1;
        __syncthreads();

        {
            const uint32_t whs = sb + SO_WH(st);
            const uint32_t ps  = sb + SO_P(pb);
#pragma unroll
            for (int kt = 0; kt < 2; kt++) {
                uint32_t af[4][4], bf[4][2];
                LDM4(bf[0][0], bf[0][1], bf[1][0], bf[1][1],
                     ps + b_off0 + kt * 32);
                LDM4(bf[2][0], bf[2][1], bf[3][0], bf[3][1],
                     ps + b_off1 + kt * 32);
#pragma unroll
                for (int mi = 0; mi < 4; mi++)
                    LDM4(af[mi][0], af[mi][1], af[mi][2], af[mi][3],
                         whs + a_off + mi * 1280 + kt * 32);
#pragma unroll
                for (int ni = 0; ni < 4; ni++)
#pragma unroll
                    for (int mi = 0; mi < 4; mi++)
                        MMA16816(c[mi][ni][0], c[mi][ni][1], c[mi][ni][2], c[mi][ni][3],
                                 af[mi][0], af[mi][1], af[mi][2], af[mi][3],
                                 bf[ni][0], bf[ni][1]);
            }
        }
    }

    // ---- row sums -> 1/l (4 threads per i-row) ----
    l_acc += __shfl_xor_sync(0xffffffffu, l_acc, 1);
    l_acc += __shfl_xor_sync(0xffffffffu, l_acc, 2);
    __syncthreads();
    if ((tid & 3) == 0) s_l[pi] = l_acc;
    __syncthreads();
    if (tid < BI) {
        float l = s_l[tid];
        s_l[tid] = (l > 0.f) ? (1.f / l) : 0.f;
    }
    __syncthreads();

    // ---- epilogue: scaled stores to transposed partials out3T[d][i] ----
    float* T = g_out3[r];
#pragma unroll
    for (int ni = 0; ni < 4; ni++) {
        int icol = nwb + ni * 8 + (lane & 3) * 2;
        float iv0 = s_l[icol];
        float iv1 = s_l[icol + 1];
#pragma unroll
        for (int mi = 0; mi < 4; mi++) {
            int d = dwb + mi * 16 + (lane >> 2);
            *(float2*)&T[(size_t)d * NN + i0 + icol] =
                make_float2(c[mi][ni][0] * iv0, c[mi][ni][1] * iv1);
            *(float2*)&T[(size_t)(d + 8) * NN + i0 + icol] =
                make_float2(c[mi][ni][2] * iv0, c[mi][ni][3] * iv1);
        }
    }
}

// ---------------------------------------------------------------------------
// Kernel 3: out[i][d] = sum_r out3T[r][d][i] + bias[d]
// ---------------------------------------------------------------------------
__global__ void __launch_bounds__(256) combine_t_kernel(
    const float* __restrict__ bias, float* __restrict__ out)
{
    const int i0 = blockIdx.x * 32;
    const int d0 = blockIdx.y * 32;
    __shared__ float t[32][33];

    const int tid = threadIdx.x;
    const int ty = tid >> 5;
    const int tx = tid & 31;

#pragma unroll
    for (int s = 0; s < 4; s++) {
        int dl = ty + s * 8;
        size_t off = (size_t)(d0 + dl) * NN + i0 + tx;
        t[dl][tx] = g_out3[0][off] + g_out3[1][off] + g_out3[2][off];
    }
    __syncthreads();

    const int il = tid >> 3;
    const int dq = (tid & 7) * 4;
    float4 b = *(const float4*)&bias[d0 + dq];
    float4 v;
    v.x = t[dq + 0][il] + b.x;
    v.y = t[dq + 1][il] + b.y;
    v.z = t[dq + 2][il] + b.z;
    v.w = t[dq + 3][il] + b.w;
    *(float4*)&out[(size_t)(i0 + il) * DD + d0 + dq] = v;
}

// ---------------------------------------------------------------------------
extern "C" void kernel_launch(void* const* d_in, const int* in_sizes, int n_in,
                              void* d_out, int out_size)
{
    const float* H    = (const float*)d_in[0];
    const float* W1   = (const float*)d_in[1];
    const float* W2   = (const float*)d_in[2];
    const float* W3   = (const float*)d_in[3];
    const float* a1   = (const float*)d_in[4];
    const float* a2   = (const float*)d_in[5];
    const float* a3   = (const float*)d_in[6];
    const float* bias = (const float*)d_in[7];
    const int*   A1   = (const int*)d_in[8];
    const int*   A2   = (const int*)d_in[9];
    const int*   A3   = (const int*)d_in[10];
    float* out = (float*)d_out;

    dim3 wh_grid(NN / 64, 3);
    whT_mma_kernel<<<wh_grid, 256>>>(H, W1, W2, W3, a1, a2, a3);

    cudaFuncSetAttribute(passb_mma_kernel,
                         cudaFuncAttributeMaxDynamicSharedMemorySize, SMEM_PB);
    dim3 pb_grid(NN / BI, 3);
    passb_mma_kernel<<<pb_grid, 256, SMEM_PB>>>(A1, A2, A3);

    dim3 cb_grid(NN / 32, DD / 32);
    combine_t_kernel<<<cb_grid, 256>>>(bias, out);
}